// round 12
// baseline (speedup 1.0000x reference)
#include <cuda_runtime.h>
#include <stdint.h>

#define NT 512            // 16 warps; 16 batch rows per warp
#define BATCH_PER_CTA 256

// ---- smem layout (bytes) ----
#define OFF_BF    0         // [2 mats][24 nt][4 kt][32 lanes] uint4 = 98304
#define OFF_STAGE 98304     // [16 warps][8 slots][32 lanes] uint4   = 65536
#define OFF_TAB   163840    // [2 mats][64 j][4] float4              = 8192
#define OFF_LWT   172032    // [64] float4                           = 1024
#define OFF_LNB   173056    // float4
#define SMEM_TOTAL 173072

// ---------------- helpers ----------------
__device__ __forceinline__ float bfhi(uint32_t u32) {
    return __uint_as_float(u32 & 0xffff0000u);
}
__device__ __forceinline__ float bflo(uint32_t u32) {
    return __uint_as_float(u32 << 16);
}
__device__ __forceinline__ uint32_t cvt2(float vhi, float vlo) {
    uint32_t r;
    asm("cvt.rn.satfinite.bf16x2.f32 %0, %1, %2;" : "=r"(r) : "f"(vhi), "f"(vlo));
    return r;
}
// split (v0 -> lo16, v1 -> hi16) into hi-part + residual-part
__device__ __forceinline__ void split2c(float v0, float v1, uint32_t& hi, uint32_t& lo) {
    hi = cvt2(v1, v0);
    float r0 = v0 - bflo(hi);
    float r1 = v1 - bfhi(hi);
    lo = cvt2(r1, r0);
}
__device__ __forceinline__ float fex2(float x) {
    float r; asm("ex2.approx.f32 %0, %1;" : "=f"(r) : "f"(x)); return r;
}
__device__ __forceinline__ float frcp(float x) {
    float r; asm("rcp.approx.f32 %0, %1;" : "=f"(r) : "f"(x)); return r;
}
__device__ __forceinline__ float fsigmoid(float x) {
    return frcp(1.0f + fex2(-1.4426950408889634f * x));
}
__device__ __forceinline__ float ftanh(float x) {
    float a = fabsf(x);
    float t = 1.0f - 2.0f * frcp(fex2(2.8853900817779268f * a) + 1.0f);
    return copysignf(t, x);
}
__device__ __forceinline__ void mma16816(float* d, const uint32_t* a,
                                         uint32_t b0, uint32_t b1) {
    asm volatile(
        "mma.sync.aligned.m16n8k16.row.col.f32.bf16.bf16.f32 "
        "{%0,%1,%2,%3}, {%4,%5,%6,%7}, {%8,%9}, {%0,%1,%2,%3};"
        : "+f"(d[0]), "+f"(d[1]), "+f"(d[2]), "+f"(d[3])
        : "r"(a[0]), "r"(a[1]), "r"(a[2]), "r"(a[3]), "r"(b0), "r"(b1));
}

// epilogue for one row, two h columns (j0, j0+1); full px/bias fold in scalar
template <bool DEC>
__device__ __forceinline__ void epi2(
    float Dr0, float Dz0, float Dn0, float Dr1, float Dz1, float Dn1,
    float4 px,
    float4 b40, float4 wir0, float4 wiz0, float4 wn0,
    float4 b41, float4 wir1, float4 wiz1, float4 wn1,
    float4 lw0, float4 lw1,
    uint32_t ah, uint32_t al, uint32_t& nh, uint32_t& nl, float4& la)
{
    float hold0 = bflo(ah) + bflo(al);
    float hold1 = bfhi(ah) + bfhi(al);

    float gr0 = Dr0 + b40.x;
    gr0 = fmaf(px.x, wir0.x, gr0); gr0 = fmaf(px.y, wir0.y, gr0);
    gr0 = fmaf(px.z, wir0.z, gr0); gr0 = fmaf(px.w, wir0.w, gr0);
    float gz0 = Dz0 + b40.y;
    gz0 = fmaf(px.x, wiz0.x, gz0); gz0 = fmaf(px.y, wiz0.y, gz0);
    gz0 = fmaf(px.z, wiz0.z, gz0); gz0 = fmaf(px.w, wiz0.w, gz0);
    float gi0 = b40.w;
    gi0 = fmaf(px.x, wn0.x, gi0); gi0 = fmaf(px.y, wn0.y, gi0);
    gi0 = fmaf(px.z, wn0.z, gi0); gi0 = fmaf(px.w, wn0.w, gi0);
    float r0 = fsigmoid(gr0);
    float z0 = fsigmoid(gz0);
    float n0 = ftanh(fmaf(r0, Dn0 + b40.z, gi0));
    float h0 = fmaf(z0, hold0 - n0, n0);

    float gr1 = Dr1 + b41.x;
    gr1 = fmaf(px.x, wir1.x, gr1); gr1 = fmaf(px.y, wir1.y, gr1);
    gr1 = fmaf(px.z, wir1.z, gr1); gr1 = fmaf(px.w, wir1.w, gr1);
    float gz1 = Dz1 + b41.y;
    gz1 = fmaf(px.x, wiz1.x, gz1); gz1 = fmaf(px.y, wiz1.y, gz1);
    gz1 = fmaf(px.z, wiz1.z, gz1); gz1 = fmaf(px.w, wiz1.w, gz1);
    float gi1 = b41.w;
    gi1 = fmaf(px.x, wn1.x, gi1); gi1 = fmaf(px.y, wn1.y, gi1);
    gi1 = fmaf(px.z, wn1.z, gi1); gi1 = fmaf(px.w, wn1.w, gi1);
    float r1 = fsigmoid(gr1);
    float z1 = fsigmoid(gz1);
    float n1 = ftanh(fmaf(r1, Dn1 + b41.z, gi1));
    float h1 = fmaf(z1, hold1 - n1, n1);

    if (DEC) {
        la.x = fmaf(h0, lw0.x, la.x); la.x = fmaf(h1, lw1.x, la.x);
        la.y = fmaf(h0, lw0.y, la.y); la.y = fmaf(h1, lw1.y, la.y);
        la.z = fmaf(h0, lw0.z, la.z); la.z = fmaf(h1, lw1.z, la.z);
        la.w = fmaf(h0, lw0.w, la.w); la.w = fmaf(h1, lw1.w, la.w);
    }
    split2c(h0, h1, nh, nl);
}

__device__ __forceinline__ void reduce4(float4& v) {
#pragma unroll
    for (int m = 1; m <= 2; m <<= 1) {
        v.x += __shfl_xor_sync(0xffffffffu, v.x, m);
        v.y += __shfl_xor_sync(0xffffffffu, v.y, m);
        v.z += __shfl_xor_sync(0xffffffffu, v.z, m);
        v.w += __shfl_xor_sync(0xffffffffu, v.w, m);
    }
}

// one GRU step for 16 batch rows (1 m-tile) owned by this warp.
// B fragments are software-pipelined one (jt,kt) slot ahead.
template <bool DEC>
__device__ __forceinline__ void gru_step(
    const uint4* bm, const float4* tab, const float4* lwt,
    uint4* stage, int tc,
    uint32_t (&aH)[4][4], uint32_t (&aL)[4][4],
    float4 px0, float4 px1, float4& la0, float4& la1)
{
    // prefetch slot (jt=0, kt=0) of each gate block
    uint4 br = bm[0];
    uint4 bz = bm[32 * 32];
    uint4 bn = bm[64 * 32];

#pragma unroll
    for (int jt = 0; jt < 8; ++jt) {
        float dr[4] = {0, 0, 0, 0}, dz[4] = {0, 0, 0, 0}, dn[4] = {0, 0, 0, 0};
#pragma unroll
        for (int kt = 0; kt < 4; ++kt) {
            uint4 cr = br, cz = bz, cn = bn;
            const int f = (jt * 4 + kt + 1) & 31;   // next slot (wraps)
            br = bm[f * 32];
            bz = bm[(32 + f) * 32];
            bn = bm[(64 + f) * 32];
            // interleaved: consecutive HMMAs hit different accumulators
            mma16816(dr, aH[kt], cr.x, cr.y);
            mma16816(dz, aH[kt], cz.x, cz.y);
            mma16816(dn, aH[kt], cn.x, cn.y);
            mma16816(dr, aL[kt], cr.x, cr.y);
            mma16816(dz, aL[kt], cz.x, cz.y);
            mma16816(dn, aL[kt], cn.x, cn.y);
            mma16816(dr, aH[kt], cr.z, cr.w);
            mma16816(dz, aH[kt], cz.z, cz.w);
            mma16816(dn, aH[kt], cn.z, cn.w);
        }
        const int j0 = jt * 8 + tc * 2;
        const float4* tj = tab + (size_t)j0 * 4;
        float4 b40 = tj[0], wir0 = tj[1], wiz0 = tj[2], wn0 = tj[3];
        float4 b41 = tj[4], wir1 = tj[5], wiz1 = tj[6], wn1 = tj[7];
        float4 lw0, lw1;
        if (DEC) { lw0 = lwt[j0]; lw1 = lwt[j0 + 1]; }
        const int kt = jt >> 1;
        const int a0 = (jt & 1) * 2;
        uint32_t h0, l0, h1, l1;
        epi2<DEC>(dr[0], dz[0], dn[0], dr[1], dz[1], dn[1], px0,
                  b40, wir0, wiz0, wn0, b41, wir1, wiz1, wn1, lw0, lw1,
                  aH[kt][a0], aL[kt][a0], h0, l0, la0);
        epi2<DEC>(dr[2], dz[2], dn[2], dr[3], dz[3], dn[3], px1,
                  b40, wir0, wiz0, wn0, b41, wir1, wiz1, wn1, lw0, lw1,
                  aH[kt][a0 + 1], aL[kt][a0 + 1], h1, l1, la1);
        stage[jt * 32] = make_uint4(h0, h1, l0, l1);
    }
    // reload new A fragments (warp-private smem; same-thread st->ld ordered)
#pragma unroll
    for (int jt = 0; jt < 8; ++jt) {
        const int kt = jt >> 1;
        const int a0 = (jt & 1) * 2;
        uint4 v = stage[jt * 32];
        aH[kt][a0] = v.x; aH[kt][a0 + 1] = v.y;
        aL[kt][a0] = v.z; aL[kt][a0 + 1] = v.w;
    }
}

__global__ void __launch_bounds__(NT, 1)
gru_encdec_mma5(const float* __restrict__ seq,
                const float* __restrict__ enc_Wih, const float* __restrict__ enc_Whh,
                const float* __restrict__ enc_bih, const float* __restrict__ enc_bhh,
                const float* __restrict__ dec_Wih, const float* __restrict__ dec_Whh,
                const float* __restrict__ dec_bih, const float* __restrict__ dec_bhh,
                const float* __restrict__ lin_W, const float* __restrict__ lin_b,
                float* __restrict__ out) {
    extern __shared__ char smem[];
    const int tid = threadIdx.x;
    const int warp = tid >> 5;
    const int lane = tid & 31;
    const int g = lane >> 2;
    const int tc = lane & 3;

    // ---------------- one-time weight prep ----------------
    uint4* bfr = (uint4*)(smem + OFF_BF);
    for (int idx = tid; idx < 2 * 24 * 4 * 32; idx += NT) {
        int li = idx & 31;
        int kt = (idx >> 5) & 3;
        int nt = (idx >> 7) % 24;
        int mat = idx / (32 * 4 * 24);
        const float* Whh = mat ? dec_Whh : enc_Whh;
        int n = nt * 8 + (li >> 2);
        int k0 = kt * 16 + (li & 3) * 2;
        float v0 = Whh[n * 64 + k0];
        float v1 = Whh[n * 64 + k0 + 1];
        float v2 = Whh[n * 64 + k0 + 8];
        float v3 = Whh[n * 64 + k0 + 9];
        uint4 q;
        split2c(v0, v1, q.x, q.z);
        split2c(v2, v3, q.y, q.w);
        bfr[idx] = q;
    }
    {
        float4* t4 = (float4*)(smem + OFF_TAB);
        for (int idx = tid; idx < 2 * 64; idx += NT) {
            int mat = idx >> 6, j = idx & 63;
            const float* Wih = mat ? dec_Wih : enc_Wih;
            const float* bih = mat ? dec_bih : enc_bih;
            const float* bhh = mat ? dec_bhh : enc_bhh;
            t4[idx * 4 + 0] = make_float4(bih[j] + bhh[j], bih[64 + j] + bhh[64 + j],
                                          bhh[128 + j], bih[128 + j]);
            t4[idx * 4 + 1] = ((const float4*)Wih)[j];
            t4[idx * 4 + 2] = ((const float4*)Wih)[64 + j];
            t4[idx * 4 + 3] = ((const float4*)Wih)[128 + j];
        }
        float4* lwt = (float4*)(smem + OFF_LWT);
        for (int j = tid; j < 64; j += NT)
            lwt[j] = make_float4(lin_W[j], lin_W[64 + j], lin_W[128 + j], lin_W[192 + j]);
        if (tid == 0) *(float4*)(smem + OFF_LNB) =
            make_float4(lin_b[0], lin_b[1], lin_b[2], lin_b[3]);
    }
    __syncthreads();

    // ---------------- per-warp state: 16 batch rows (rows g, g+8) -----------
    const int r0 = blockIdx.x * BATCH_PER_CTA + warp * 16 + g;
    const float4* sq = (const float4*)seq + (size_t)r0 * 51;
    float4* ob = (float4*)out + (size_t)r0 * 20;
    const float4* lwt = (const float4*)(smem + OFF_LWT);
    uint4* stage = (uint4*)(smem + OFF_STAGE) + warp * 256 + lane;

    uint32_t aH[4][4], aL[4][4];
#pragma unroll
    for (int k = 0; k < 4; ++k)
#pragma unroll
        for (int r = 0; r < 4; ++r) { aH[k][r] = 0; aL[k][r] = 0; }

    float4 px0 = make_float4(0, 0, 0, 0), px1 = px0;
    float4 la0, la1;

    // ---------------- encoder: 50 steps ----------------
    const uint4* bmE = bfr + lane;
    const float4* tabE = (const float4*)(smem + OFF_TAB);
#pragma unroll 1
    for (int t = 0; t < 50; ++t) {
        float4 a, b;
        a = sq[t];       b = sq[t + 1];
        px0 = make_float4(b.x - a.x, b.y - a.y, b.z - a.z, b.w - a.w);
        a = sq[408 + t]; b = sq[409 + t];
        px1 = make_float4(b.x - a.x, b.y - a.y, b.z - a.z, b.w - a.w);
        gru_step<false>(bmE, tabE, lwt, stage, tc, aH, aL, px0, px1, la0, la1);
    }

    // ---------------- decoder: 20 steps ----------------
    const uint4* bmD = bfr + 24 * 4 * 32 + lane;
    const float4* tabD = tabE + 64 * 4;
    const float4 lnb = *(const float4*)(smem + OFF_LNB);
    const float4 of0 = sq[50], of1 = sq[458];

#pragma unroll 1
    for (int s = 0; s < 20; ++s) {
        la0 = make_float4(0, 0, 0, 0); la1 = la0;
        gru_step<true>(bmD, tabD, lwt, stage, tc, aH, aL, px0, px1, la0, la1);
        reduce4(la0); reduce4(la1);
        float4 x0 = make_float4(la0.x + lnb.x + px0.x, la0.y + lnb.y + px0.y,
                                la0.z + lnb.z + px0.z, la0.w + lnb.w + px0.w);
        float4 x1 = make_float4(la1.x + lnb.x + px1.x, la1.y + lnb.y + px1.y,
                                la1.z + lnb.z + px1.z, la1.w + lnb.w + px1.w);
        px0 = x0; px1 = x1;
        if (tc == 0) {
            ob[s]       = make_float4(x0.x + of0.x, x0.y + of0.y,
                                      x0.z + of0.z, x0.w + of0.w);
            ob[s + 160] = make_float4(x1.x + of1.x, x1.y + of1.y,
                                      x1.z + of1.z, x1.w + of1.w);
        }
    }
}

extern "C" void kernel_launch(void* const* d_in, const int* in_sizes, int n_in,
                              void* d_out, int out_size) {
    const float* seq     = (const float*)d_in[0];
    const float* enc_Wih = (const float*)d_in[1];
    const float* enc_Whh = (const float*)d_in[2];
    const float* enc_bih = (const float*)d_in[3];
    const float* enc_bhh = (const float*)d_in[4];
    const float* dec_Wih = (const float*)d_in[5];
    const float* dec_Whh = (const float*)d_in[6];
    const float* dec_bih = (const float*)d_in[7];
    const float* dec_bhh = (const float*)d_in[8];
    const float* lin_W   = (const float*)d_in[9];
    const float* lin_b   = (const float*)d_in[10];
    float* out = (float*)d_out;

    cudaFuncSetAttribute(gru_encdec_mma5,
                         cudaFuncAttributeMaxDynamicSharedMemorySize, SMEM_TOTAL);

    const int B = 131072;
    gru_encdec_mma5<<<B / BATCH_PER_CTA, NT, SMEM_TOTAL>>>(
        seq, enc_Wih, enc_Whh, enc_bih, enc_bhh,
        dec_Wih, dec_Whh, dec_bih, dec_bhh, lin_W, lin_b, out);
}